// round 1
// baseline (speedup 1.0000x reference)
#include <cuda_runtime.h>
#include <math.h>

// Problem constants
#define Bb 8
#define Nn 2048
#define Dd 512
#define Pp 16
#define Hh 32
#define PH (Pp*Hh)     // 512
#define ROWS (Bb*Nn)   // 16384

// SGEMM tiling
#define BM 128
#define BN 128
#define BK 8
#define TM 8
#define TN 8

// Scratch: G = relu(context @ W^T), stacked over personas. 16384 x 512 fp32.
__device__ float g_G[(size_t)ROWS * PH];
__device__ float g_rmax[ROWS];
__device__ float g_rinv[ROWS];

// C[m,n] = f(alpha * sum_k A[m,k]*B[n,k]); A: MxK row-major, B: NxK row-major.
// Requires M%128==0, N%128==0, K%8==0 (true for all our shapes).
template<bool RELU>
__global__ __launch_bounds__(256)
void sgemm_abt(const float* __restrict__ Ag, const float* __restrict__ Bg,
               float* __restrict__ Cg, int M, int N, int K,
               size_t strideA, size_t strideB, size_t strideC, float alpha)
{
    const float* A = Ag + (size_t)blockIdx.z * strideA;
    const float* B = Bg + (size_t)blockIdx.z * strideB;
    float*       C = Cg + (size_t)blockIdx.z * strideC;

    __shared__ __align__(16) float As[2][BK][BM];
    __shared__ __align__(16) float Bs[2][BK][BN];

    const int tid  = threadIdx.x;
    const int lrow = tid >> 1;         // 0..127: tile row loaded by this thread
    const int lk4  = (tid & 1) * 4;    // 0 or 4: k sub-offset

    const int tx = tid & 15;           // N micro-tile index
    const int ty = tid >> 4;           // M micro-tile index

    const int m0 = blockIdx.y * BM;
    const int n0 = blockIdx.x * BN;

    const float* Aptr = A + (size_t)(m0 + lrow) * K + lk4;
    const float* Bptr = B + (size_t)(n0 + lrow) * K + lk4;

    float acc[TM][TN];
#pragma unroll
    for (int i = 0; i < TM; i++)
#pragma unroll
        for (int j = 0; j < TN; j++) acc[i][j] = 0.f;

    const int nk = K / BK;

    // preload tile 0
    float4 a = *(const float4*)(Aptr);
    float4 b = *(const float4*)(Bptr);
    As[0][lk4+0][lrow]=a.x; As[0][lk4+1][lrow]=a.y; As[0][lk4+2][lrow]=a.z; As[0][lk4+3][lrow]=a.w;
    Bs[0][lk4+0][lrow]=b.x; Bs[0][lk4+1][lrow]=b.y; Bs[0][lk4+2][lrow]=b.z; Bs[0][lk4+3][lrow]=b.w;
    __syncthreads();

    for (int kt = 0; kt < nk; ++kt) {
        const int cur = kt & 1;
        const int nxt = cur ^ 1;
        if (kt + 1 < nk) {
            a = *(const float4*)(Aptr + (size_t)(kt + 1) * BK);
            b = *(const float4*)(Bptr + (size_t)(kt + 1) * BK);
        }
#pragma unroll
        for (int k = 0; k < BK; k++) {
            float4 a0 = *(const float4*)(&As[cur][k][ty*TM]);
            float4 a1 = *(const float4*)(&As[cur][k][ty*TM+4]);
            float4 b0 = *(const float4*)(&Bs[cur][k][tx*TN]);
            float4 b1 = *(const float4*)(&Bs[cur][k][tx*TN+4]);
            float ra[TM] = {a0.x,a0.y,a0.z,a0.w,a1.x,a1.y,a1.z,a1.w};
            float rb[TN] = {b0.x,b0.y,b0.z,b0.w,b1.x,b1.y,b1.z,b1.w};
#pragma unroll
            for (int i = 0; i < TM; i++)
#pragma unroll
                for (int j = 0; j < TN; j++)
                    acc[i][j] = fmaf(ra[i], rb[j], acc[i][j]);
        }
        if (kt + 1 < nk) {
            As[nxt][lk4+0][lrow]=a.x; As[nxt][lk4+1][lrow]=a.y; As[nxt][lk4+2][lrow]=a.z; As[nxt][lk4+3][lrow]=a.w;
            Bs[nxt][lk4+0][lrow]=b.x; Bs[nxt][lk4+1][lrow]=b.y; Bs[nxt][lk4+2][lrow]=b.z; Bs[nxt][lk4+3][lrow]=b.w;
        }
        __syncthreads();
    }

#pragma unroll
    for (int i = 0; i < TM; i++) {
        const size_t row = (size_t)(m0 + ty*TM + i);
        float* cp = C + row * (size_t)N + n0 + tx*TN;
#pragma unroll
        for (int j = 0; j < TN; j += 4) {
            float4 v;
            v.x = acc[i][j+0] * alpha;
            v.y = acc[i][j+1] * alpha;
            v.z = acc[i][j+2] * alpha;
            v.w = acc[i][j+3] * alpha;
            if (RELU) {
                v.x = fmaxf(v.x, 0.f); v.y = fmaxf(v.y, 0.f);
                v.z = fmaxf(v.z, 0.f); v.w = fmaxf(v.w, 0.f);
            }
            *(float4*)(cp + j) = v;
        }
    }
}

// Per-row max and 1/sum(exp(x-max)) over the 2048 columns of S.
// By symmetry of S these are also the per-COLUMN stats the softmax(axis=1) needs.
__global__ __launch_bounds__(256)
void row_stats_kernel(const float* __restrict__ S)
{
    const int row = blockIdx.x;           // b*2048 + m
    const int tid = threadIdx.x;
    const float4* p = (const float4*)(S + (size_t)row * Nn);
    float4 v1 = p[tid];
    float4 v2 = p[tid + 256];

    float mx = fmaxf(fmaxf(fmaxf(v1.x, v1.y), fmaxf(v1.z, v1.w)),
                     fmaxf(fmaxf(v2.x, v2.y), fmaxf(v2.z, v2.w)));

    __shared__ float red[8];
#pragma unroll
    for (int o = 16; o > 0; o >>= 1)
        mx = fmaxf(mx, __shfl_xor_sync(0xffffffffu, mx, o));
    if ((tid & 31) == 0) red[tid >> 5] = mx;
    __syncthreads();
    mx = red[0];
#pragma unroll
    for (int i = 1; i < 8; i++) mx = fmaxf(mx, red[i]);
    __syncthreads();   // before reusing red[]

    float s = __expf(v1.x - mx) + __expf(v1.y - mx) + __expf(v1.z - mx) + __expf(v1.w - mx)
            + __expf(v2.x - mx) + __expf(v2.y - mx) + __expf(v2.z - mx) + __expf(v2.w - mx);
#pragma unroll
    for (int o = 16; o > 0; o >>= 1)
        s += __shfl_xor_sync(0xffffffffu, s, o);
    if ((tid & 31) == 0) red[tid >> 5] = s;
    __syncthreads();
    if (tid == 0) {
        float t = 0.f;
#pragma unroll
        for (int i = 0; i < 8; i++) t += red[i];
        g_rmax[row] = mx;
        g_rinv[row] = 1.f / t;
    }
}

// In-place: out[b,n,m] = exp(S[b,n,m] - rmax[b,m]) * rinv[b,m] * mask[b,n] * mask[b,m]
__global__ __launch_bounds__(256)
void norm_mask_kernel(float* __restrict__ S, const int* __restrict__ mask)
{
    const int row = blockIdx.x;           // b*2048 + n
    const int tid = threadIdx.x;
    const int b   = row >> 11;
    const float mn = (float)mask[row];    // mask[b,n]

    const float4* rmax = (const float4*)(g_rmax + ((size_t)b << 11));
    const float4* rinv = (const float4*)(g_rinv + ((size_t)b << 11));
    const int4*   mrow = (const int4*)(mask + ((size_t)b << 11));
    float4* p = (float4*)(S + (size_t)row * Nn);

#pragma unroll
    for (int jj = 0; jj < 2; jj++) {
        const int j = tid + jj * 256;     // 512 float4 per row
        float4 v  = p[j];
        float4 mx = rmax[j];
        float4 iv = rinv[j];
        int4   mm = mrow[j];
        v.x = __expf(v.x - mx.x) * iv.x * mn * (float)mm.x;
        v.y = __expf(v.y - mx.y) * iv.y * mn * (float)mm.y;
        v.z = __expf(v.z - mx.z) * iv.z * mn * (float)mm.z;
        v.w = __expf(v.w - mx.w) * iv.w * mn * (float)mm.w;
        p[j] = v;
    }
}

extern "C" void kernel_launch(void* const* d_in, const int* in_sizes, int n_in,
                              void* d_out, int out_size)
{
    const float* ctx  = (const float*)d_in[0];   // [8, 2048, 512]
    const float* W    = (const float*)d_in[1];   // [16, 32, 512] == [512, 512]
    const int*   mask = (const int*)d_in[2];     // [8, 2048]
    float* out = (float*)d_out;                  // [8, 2048, 2048]

    void* gsym = nullptr;
    cudaGetSymbolAddress(&gsym, g_G);
    float* G = (float*)gsym;

    // K1: G = relu(context @ W^T)   [16384,512] x [512,512]^T
    {
        dim3 grid(PH / BN, ROWS / BM, 1);
        sgemm_abt<true><<<grid, 256>>>(ctx, W, G, ROWS, PH, Dd, 0, 0, 0, 1.0f);
    }
    // K2: S_b = G_b @ G_b^T / 16  -> written directly into d_out
    {
        dim3 grid(Nn / BN, Nn / BM, Bb);
        sgemm_abt<false><<<grid, 256>>>(G, G, out, Nn, Nn, PH,
                                        (size_t)Nn * PH, (size_t)Nn * PH,
                                        (size_t)Nn * Nn, 1.0f / (float)Pp);
    }
    // K3: per-row (== per-column, by symmetry) softmax stats
    row_stats_kernel<<<ROWS, 256>>>(out);
    // K4: in-place normalize + mask
    norm_mask_kernel<<<ROWS, 256>>>(out, mask);
}

// round 3
// speedup vs baseline: 1.9134x; 1.9134x over previous
#include <cuda_runtime.h>
#include <cuda_bf16.h>
#include <stdint.h>
#include <math.h>

#define Bb 8
#define Nn 2048
#define Dd 512
#define Pp 16
#define PH 512
#define ROWS (Bb*Nn)   // 16384

// ---------------- scratch ---------------------------------------------------
__device__ __nv_bfloat16 g_ctx_h[(size_t)ROWS * Dd];
__device__ __nv_bfloat16 g_ctx_l[(size_t)ROWS * Dd];
__device__ __nv_bfloat16 g_W_h[(size_t)PH * Dd];
__device__ __nv_bfloat16 g_W_l[(size_t)PH * Dd];
__device__ __nv_bfloat16 g_G_h[(size_t)ROWS * PH];
__device__ __nv_bfloat16 g_G_l[(size_t)ROWS * PH];
__device__ float g_rmax[ROWS];
__device__ float g_rinv[ROWS];

// ---------------- small PTX helpers (all base-ISA, no 'a' features) --------
__device__ __forceinline__ uint32_t smem_u32(const void* p) {
    uint32_t a;
    asm("{ .reg .u64 t; cvta.to.shared.u64 t, %1; cvt.u32.u64 %0, t; }" : "=r"(a) : "l"(p));
    return a;
}
__device__ __forceinline__ void cpa16(uint32_t saddr, const void* g) {
    asm volatile("cp.async.cg.shared.global [%0], [%1], 16;" :: "r"(saddr), "l"(g));
}
#define CP_COMMIT() asm volatile("cp.async.commit_group;" ::: "memory")
#define CP_WAIT(n)  asm volatile("cp.async.wait_group %0;" :: "n"(n) : "memory")

__device__ __forceinline__ void ldsm4(uint32_t& d0, uint32_t& d1, uint32_t& d2, uint32_t& d3,
                                      uint32_t addr) {
    asm volatile("ldmatrix.sync.aligned.m8n8.x4.shared.b16 {%0,%1,%2,%3}, [%4];"
                 : "=r"(d0), "=r"(d1), "=r"(d2), "=r"(d3) : "r"(addr));
}
__device__ __forceinline__ void mma_bf16(float* c, const uint32_t* a, uint32_t b0, uint32_t b1) {
    asm volatile("mma.sync.aligned.m16n8k16.row.col.f32.bf16.bf16.f32 "
                 "{%0,%1,%2,%3}, {%4,%5,%6,%7}, {%8,%9}, {%0,%1,%2,%3};"
                 : "+f"(c[0]), "+f"(c[1]), "+f"(c[2]), "+f"(c[3])
                 : "r"(a[0]), "r"(a[1]), "r"(a[2]), "r"(a[3]), "r"(b0), "r"(b1));
}

// ---------------- split fp32 -> (hi, lo) bf16 ------------------------------
__global__ __launch_bounds__(256)
void split_kernel(const float* __restrict__ x, __nv_bfloat16* __restrict__ h,
                  __nv_bfloat16* __restrict__ l, int n4)
{
    int i = blockIdx.x * blockDim.x + threadIdx.x;
    if (i >= n4) return;
    float4 v = ((const float4*)x)[i];
    __nv_bfloat16 h0 = __float2bfloat16(v.x), h1 = __float2bfloat16(v.y);
    __nv_bfloat16 h2 = __float2bfloat16(v.z), h3 = __float2bfloat16(v.w);
    __nv_bfloat16 l0 = __float2bfloat16(v.x - __bfloat162float(h0));
    __nv_bfloat16 l1 = __float2bfloat16(v.y - __bfloat162float(h1));
    __nv_bfloat16 l2 = __float2bfloat16(v.z - __bfloat162float(h2));
    __nv_bfloat16 l3 = __float2bfloat16(v.w - __bfloat162float(h3));
    __nv_bfloat162 hp0 = __halves2bfloat162(h0, h1), hp1 = __halves2bfloat162(h2, h3);
    __nv_bfloat162 lp0 = __halves2bfloat162(l0, l1), lp1 = __halves2bfloat162(l2, l3);
    uint2 hv, lv;
    hv.x = *(uint32_t*)&hp0; hv.y = *(uint32_t*)&hp1;
    lv.x = *(uint32_t*)&lp0; lv.y = *(uint32_t*)&lp1;
    ((uint2*)h)[i] = hv;
    ((uint2*)l)[i] = lv;
}

// ---------------- mma.sync GEMM: C = f(alpha * A·B^T), 2-term bf16 split ---
// A,B row-major [*, 512] bf16 (hi+lo pair). CTA tile 128x128, BK=32.
// 3 accumulation passes over K: Ahi·Bhi^T + Ahi·Blo^T + Alo·Bhi^T.
// EPI=0: store fp32 * alpha. EPI=1: relu, split into (Ch, Cl) bf16.
#define LDS_ROW 40          // 32 bf16 + 8 pad = 80 bytes
#define ROWB    80
#define NIT     48          // 3 terms * (512/32)

template<int EPI>
__global__ __launch_bounds__(256, 2)
void mma_gemm(const __nv_bfloat16* __restrict__ Ah, const __nv_bfloat16* __restrict__ Al,
              const __nv_bfloat16* __restrict__ Bh, const __nv_bfloat16* __restrict__ Bl,
              float* __restrict__ Cf, __nv_bfloat16* __restrict__ Ch, __nv_bfloat16* __restrict__ Cl,
              int Ncols, size_t sA, size_t sB, size_t sC, float alpha)
{
    __shared__ __align__(16) __nv_bfloat16 As[2][128 * LDS_ROW];
    __shared__ __align__(16) __nv_bfloat16 Bs[2][128 * LDS_ROW];

    const int tid  = threadIdx.x;
    const int wid  = tid >> 5;
    const int lane = tid & 31;
    const int wm   = wid >> 2;        // 0..1  (M warp row, 64 rows each)
    const int wn   = wid & 3;         // 0..3  (N warp col, 32 cols each)

    const int m0 = blockIdx.y * 128;
    const int n0 = blockIdx.x * 128;
    const size_t zAb = (size_t)blockIdx.z * sA * 2;   // bytes
    const size_t zBb = (size_t)blockIdx.z * sB * 2;
    const size_t zC  = (size_t)blockIdx.z * sC;

    // --- load geometry: 512 16B-chunks per 128x32 tile; this thread does 2 ---
    const int r0 = tid >> 2;          // row 0..63
    const int c0 = tid & 3;           // 16B chunk within 64B row
    const uint32_t s_off0 = (uint32_t)r0 * ROWB + (uint32_t)c0 * 16;
    const size_t   a_off0 = (size_t)(m0 + r0) * 1024 + (size_t)c0 * 16;  // K row = 1024B
    const size_t   b_off0 = (size_t)(n0 + r0) * 1024 + (size_t)c0 * 16;

    const uint32_t as_b[2] = { smem_u32(&As[0][0]), smem_u32(&As[1][0]) };
    const uint32_t bs_b[2] = { smem_u32(&Bs[0][0]), smem_u32(&Bs[1][0]) };

    const char* Ahb = (const char*)Ah + zAb;
    const char* Alb = (const char*)Al + zAb;
    const char* Bhb = (const char*)Bh + zBb;
    const char* Blb = (const char*)Bl + zBb;

    float acc[4][4][4];
#pragma unroll
    for (int i = 0; i < 4; i++)
#pragma unroll
        for (int j = 0; j < 4; j++)
#pragma unroll
            for (int k = 0; k < 4; k++) acc[i][j][k] = 0.f;

    // ldmatrix per-lane geometry
    const int rA = wm * 64 + (lane & 15);     // A row within tile for this lane
    const int rB = wn * 32 + (lane & 15);     // B row within tile
    const uint32_t half16 = (uint32_t)(lane >> 4) * 16;   // 16B column-half

    auto prefetch = [&](int it, int buf) {
        const int term = it >> 4;             // 0,1,2
        const int kc   = it & 15;
        const char* Ab = (term == 2) ? Alb : Ahb;
        const char* Bbp = (term == 1) ? Blb : Bhb;
        const size_t koff = (size_t)kc * 64;  // 32 bf16 = 64B
        uint32_t sa = as_b[buf] + s_off0;
        uint32_t sb = bs_b[buf] + s_off0;
        cpa16(sa,             Ab  + a_off0 + koff);
        cpa16(sa + 64 * ROWB, Ab  + a_off0 + (size_t)64 * 1024 + koff);
        cpa16(sb,             Bbp + b_off0 + koff);
        cpa16(sb + 64 * ROWB, Bbp + b_off0 + (size_t)64 * 1024 + koff);
    };

    prefetch(0, 0); CP_COMMIT();
    prefetch(1, 1); CP_COMMIT();

    for (int it = 0; it < NIT; ++it) {
        const int buf = it & 1;
        if (it == NIT - 1) { CP_WAIT(0); } else { CP_WAIT(1); }
        __syncthreads();

        // compute the 128x128x32 block in smem buf
#pragma unroll
        for (int ks = 0; ks < 2; ks++) {
            uint32_t a[4][4];
            uint32_t b[2][4];
#pragma unroll
            for (int mi = 0; mi < 4; mi++) {
                uint32_t addr = as_b[buf] + (uint32_t)(rA + mi * 16) * ROWB
                              + (uint32_t)ks * 32 + half16;
                ldsm4(a[mi][0], a[mi][1], a[mi][2], a[mi][3], addr);
            }
#pragma unroll
            for (int nb = 0; nb < 2; nb++) {
                uint32_t addr = bs_b[buf] + (uint32_t)(rB + nb * 16) * ROWB
                              + (uint32_t)ks * 32 + half16;
                ldsm4(b[nb][0], b[nb][1], b[nb][2], b[nb][3], addr);
            }
            // b fragment for n8 group g: g=2*nb+h -> (b[nb][h], b[nb][h+2])
#pragma unroll
            for (int mi = 0; mi < 4; mi++)
#pragma unroll
                for (int g = 0; g < 4; g++)
                    mma_bf16(acc[mi][g], a[mi], b[g >> 1][g & 1], b[g >> 1][(g & 1) + 2]);
        }
        __syncthreads();
        if (it + 2 < NIT) { prefetch(it + 2, buf); CP_COMMIT(); }
    }

    // ---------------- epilogue ----------------
    const int er = m0 + wm * 64 + (lane >> 2);      // first output row
    const int ec = n0 + wn * 32 + (lane & 3) * 2;   // output col (pair)
#pragma unroll
    for (int mi = 0; mi < 4; mi++) {
#pragma unroll
        for (int g = 0; g < 4; g++) {
            const int r = er + mi * 16;
            const int c = ec + g * 8;
            if (EPI == 0) {
                float2 v0 = make_float2(acc[mi][g][0] * alpha, acc[mi][g][1] * alpha);
                float2 v1 = make_float2(acc[mi][g][2] * alpha, acc[mi][g][3] * alpha);
                *(float2*)(Cf + zC + (size_t)r * Ncols + c)       = v0;
                *(float2*)(Cf + zC + (size_t)(r + 8) * Ncols + c) = v1;
            } else {
#pragma unroll
                for (int hrow = 0; hrow < 2; hrow++) {
                    float v0 = fmaxf(acc[mi][g][2 * hrow + 0], 0.f);
                    float v1 = fmaxf(acc[mi][g][2 * hrow + 1], 0.f);
                    __nv_bfloat16 h0 = __float2bfloat16(v0), h1 = __float2bfloat16(v1);
                    __nv_bfloat16 l0 = __float2bfloat16(v0 - __bfloat162float(h0));
                    __nv_bfloat16 l1 = __float2bfloat16(v1 - __bfloat162float(h1));
                    __nv_bfloat162 hp = __halves2bfloat162(h0, h1);
                    __nv_bfloat162 lp = __halves2bfloat162(l0, l1);
                    const size_t o = (size_t)(r + 8 * hrow) * Ncols + c;
                    *(uint32_t*)(Ch + o) = *(uint32_t*)&hp;
                    *(uint32_t*)(Cl + o) = *(uint32_t*)&lp;
                }
            }
        }
    }
}

// ---------------- softmax stats / normalize --------------------------------
__global__ __launch_bounds__(256)
void row_stats_kernel(const float* __restrict__ S)
{
    const int row = blockIdx.x;
    const int tid = threadIdx.x;
    const float4* p = (const float4*)(S + (size_t)row * Nn);
    float4 v1 = p[tid];
    float4 v2 = p[tid + 256];

    float mx = fmaxf(fmaxf(fmaxf(v1.x, v1.y), fmaxf(v1.z, v1.w)),
                     fmaxf(fmaxf(v2.x, v2.y), fmaxf(v2.z, v2.w)));
    __shared__ float red[8];
#pragma unroll
    for (int o = 16; o > 0; o >>= 1)
        mx = fmaxf(mx, __shfl_xor_sync(0xffffffffu, mx, o));
    if ((tid & 31) == 0) red[tid >> 5] = mx;
    __syncthreads();
    mx = red[0];
#pragma unroll
    for (int i = 1; i < 8; i++) mx = fmaxf(mx, red[i]);
    __syncthreads();

    float s = __expf(v1.x - mx) + __expf(v1.y - mx) + __expf(v1.z - mx) + __expf(v1.w - mx)
            + __expf(v2.x - mx) + __expf(v2.y - mx) + __expf(v2.z - mx) + __expf(v2.w - mx);
#pragma unroll
    for (int o = 16; o > 0; o >>= 1)
        s += __shfl_xor_sync(0xffffffffu, s, o);
    if ((tid & 31) == 0) red[tid >> 5] = s;
    __syncthreads();
    if (tid == 0) {
        float t = 0.f;
#pragma unroll
        for (int i = 0; i < 8; i++) t += red[i];
        g_rmax[row] = mx;
        g_rinv[row] = 1.f / t;
    }
}

__global__ __launch_bounds__(256)
void norm_mask_kernel(float* __restrict__ S, const int* __restrict__ mask)
{
    const int row = blockIdx.x;
    const int tid = threadIdx.x;
    const int b   = row >> 11;
    const float mn = (float)mask[row];

    const float4* rmax = (const float4*)(g_rmax + ((size_t)b << 11));
    const float4* rinv = (const float4*)(g_rinv + ((size_t)b << 11));
    const int4*   mrow = (const int4*)(mask + ((size_t)b << 11));
    float4* p = (float4*)(S + (size_t)row * Nn);

#pragma unroll
    for (int jj = 0; jj < 2; jj++) {
        const int j = tid + jj * 256;
        float4 v  = p[j];
        float4 mx = rmax[j];
        float4 iv = rinv[j];
        int4   mm = mrow[j];
        v.x = __expf(v.x - mx.x) * iv.x * mn * (float)mm.x;
        v.y = __expf(v.y - mx.y) * iv.y * mn * (float)mm.y;
        v.z = __expf(v.z - mx.z) * iv.z * mn * (float)mm.z;
        v.w = __expf(v.w - mx.w) * iv.w * mn * (float)mm.w;
        p[j] = v;
    }
}

// ---------------- launch ---------------------------------------------------
extern "C" void kernel_launch(void* const* d_in, const int* in_sizes, int n_in,
                              void* d_out, int out_size)
{
    const float* ctx  = (const float*)d_in[0];   // [8, 2048, 512]
    const float* W    = (const float*)d_in[1];   // [16, 32, 512]
    const int*   mask = (const int*)d_in[2];     // [8, 2048]
    float* out = (float*)d_out;                  // [8, 2048, 2048]

    void *p_ch, *p_cl, *p_wh, *p_wl, *p_gh, *p_gl;
    cudaGetSymbolAddress(&p_ch, g_ctx_h); cudaGetSymbolAddress(&p_cl, g_ctx_l);
    cudaGetSymbolAddress(&p_wh, g_W_h);   cudaGetSymbolAddress(&p_wl, g_W_l);
    cudaGetSymbolAddress(&p_gh, g_G_h);   cudaGetSymbolAddress(&p_gl, g_G_l);
    __nv_bfloat16* Ch = (__nv_bfloat16*)p_ch; __nv_bfloat16* Cl = (__nv_bfloat16*)p_cl;
    __nv_bfloat16* Wh = (__nv_bfloat16*)p_wh; __nv_bfloat16* Wl = (__nv_bfloat16*)p_wl;
    __nv_bfloat16* Gh = (__nv_bfloat16*)p_gh; __nv_bfloat16* Gl = (__nv_bfloat16*)p_gl;

    // K0: split inputs into hi/lo bf16
    {
        int n4 = ROWS * Dd / 4;
        split_kernel<<<(n4 + 255) / 256, 256>>>(ctx, Ch, Cl, n4);
        int w4 = PH * Dd / 4;
        split_kernel<<<(w4 + 255) / 256, 256>>>(W, Wh, Wl, w4);
    }
    // K1: G = relu(ctx @ W^T)  -> Gh/Gl bf16 split (fused epilogue)
    {
        dim3 grid(PH / 128, ROWS / 128, 1);
        mma_gemm<1><<<grid, 256>>>(Ch, Cl, Wh, Wl, nullptr, Gh, Gl,
                                   PH, 0, 0, 0, 1.0f);
    }
    // K2: S_b = G_b @ G_b^T / 16 -> d_out (fp32 logits)
    {
        dim3 grid(Nn / 128, Nn / 128, Bb);
        mma_gemm<0><<<grid, 256>>>(Gh, Gl, Gh, Gl, out, nullptr, nullptr,
                                   Nn, (size_t)Nn * PH, (size_t)Nn * PH,
                                   (size_t)Nn * Nn, 1.0f / (float)Pp);
    }
    // K3/K4: symmetric softmax (row stats == col stats) + mask
    row_stats_kernel<<<ROWS, 256>>>(out);
    norm_mask_kernel<<<ROWS, 256>>>(out, mask);
}